// round 14
// baseline (speedup 1.0000x reference)
#include <cuda_runtime.h>
#include <stdint.h>
#include <math.h>

#define T_  2048
#define D_  768
#define L_  12
#define H_  12
#define DK_ 64
#define FF_ 2048
#define V_  50304
#define KC  4
#define EPSF 1e-6f

// ---------------- scratch (device globals; no runtime allocation) ----------------
__device__ float g_h  [T_*D_];
__device__ float g_x  [T_*D_];
__device__ float g_qp [T_*D_];
__device__ float g_kp [T_*D_];
__device__ float g_vp [T_*D_];
__device__ float g_q  [T_*D_];
__device__ float g_k  [T_*D_];
__device__ float g_v  [T_*D_];
__device__ float g_o  [T_*D_];
__device__ float g_y  [T_*D_];
__device__ float g_gate[T_*FF_];
__device__ float g_up  [T_*FF_];
__device__ float g_beta[T_*H_];
__device__ float g_loss, g_cnt;
__device__ float g_logits_fb[(size_t)T_*V_];

// ---------------- small kernels ----------------
__global__ void embed_k(const int* __restrict__ idx, const float* __restrict__ embed,
                        float* __restrict__ h) {
    int i = blockIdx.x * blockDim.x + threadIdx.x;
    if (i < T_ * D_) {
        int t = i / D_, d = i % D_;
        h[i] = embed[(size_t)idx[t] * D_ + d];
    }
}

__global__ void rmsnorm_k(const float* __restrict__ x, const float* __restrict__ w,
                          float* __restrict__ y) {
    int t = blockIdx.x;
    __shared__ float red[256];
    float ss = 0.f;
    for (int d = threadIdx.x; d < D_; d += 256) { float v = x[t*D_+d]; ss += v*v; }
    red[threadIdx.x] = ss; __syncthreads();
    for (int s = 128; s > 0; s >>= 1) {
        if (threadIdx.x < s) red[threadIdx.x] += red[threadIdx.x + s];
        __syncthreads();
    }
    float r = rsqrtf(red[0] / D_ + EPSF);
    for (int d = threadIdx.x; d < D_; d += 256) y[t*D_+d] = x[t*D_+d] * r * w[d];
}

// beta = sigmoid(x @ Wb): warp per token row, all 12 heads per warp.
__global__ __launch_bounds__(256)
void beta_k(const float* __restrict__ x, const float* __restrict__ Wb,
            float* __restrict__ beta) {
    int warp = threadIdx.x >> 5, lane = threadIdx.x & 31;
    int t = blockIdx.x * 8 + warp;
    if (t >= T_) return;
    float xv[24];
    #pragma unroll
    for (int j = 0; j < 24; j++) xv[j] = x[t * D_ + lane + 32 * j];
    #pragma unroll
    for (int h = 0; h < H_; h++) {
        float acc = 0.f;
        #pragma unroll
        for (int j = 0; j < 24; j++) acc += xv[j] * Wb[(lane + 32 * j) * H_ + h];
        #pragma unroll
        for (int s = 16; s > 0; s >>= 1) acc += __shfl_xor_sync(0xffffffffu, acc, s);
        if (lane == 0) beta[t * H_ + h] = 1.f / (1.f + expf(-acc));
    }
}

// ---------------- split-tf32 tensor-core GEMM, 4-stage cp.async pipeline -----
// CTA tile 64x128x16; 128 threads = 4 warps (2M x 2N), warp tile 32x64.
// Term-major mma issue: same-accumulator mma are 16 apart (no dep stalls).
__device__ __forceinline__ unsigned int f2tf32(float f) {
    unsigned int r;
    asm("cvt.rna.tf32.f32 %0, %1;" : "=r"(r) : "f"(f));
    return r;
}
__device__ __forceinline__ void split_tf32(float f, unsigned int& hi, unsigned int& lo) {
    hi = f2tf32(f);
    lo = f2tf32(f - __uint_as_float(hi));
}
__device__ __forceinline__ void cp16(void* smem, const void* gmem) {
    unsigned int sa = (unsigned int)__cvta_generic_to_shared(smem);
    asm volatile("cp.async.ca.shared.global [%0], [%1], 16;" :: "r"(sa), "l"(gmem));
}
#define CP_COMMIT() asm volatile("cp.async.commit_group;")
#define CP_WAIT2()  asm volatile("cp.async.wait_group 2;")

#define MMA_TF32(acc, a0,a1,a2,a3, b0,b1)                                     \
    asm volatile(                                                             \
        "mma.sync.aligned.m16n8k8.row.col.f32.tf32.tf32.f32 "                 \
        "{%0,%1,%2,%3}, {%4,%5,%6,%7}, {%8,%9}, {%0,%1,%2,%3};\n"             \
        : "+f"(acc[0]), "+f"(acc[1]), "+f"(acc[2]), "+f"(acc[3])              \
        : "r"(a0), "r"(a1), "r"(a2), "r"(a3), "r"(b0), "r"(b1))

__device__ __forceinline__
void gemm_core(int M, int N, int K,
               const float* __restrict__ A, const float* __restrict__ B,
               float* __restrict__ C, int accum,
               int row0, int col0,
               float (*Asm)[64][20], float (*Bsm)[16][136]) {
    int tid = threadIdx.x;
    int lane = tid & 31, warp = tid >> 5;
    int warpM = warp & 1, warpN = warp >> 1;    // 2 x 2 warps, warp tile 32x64
    int gid = lane >> 2, tig = lane & 3;

    float acc[2][8][4];
    #pragma unroll
    for (int mt = 0; mt < 2; mt++)
        #pragma unroll
        for (int nt = 0; nt < 8; nt++)
            #pragma unroll
            for (int i = 0; i < 4; i++) acc[mt][nt][i] = 0.f;

    int aRow = tid >> 1, aKq = (tid & 1) * 8;
    int bK = tid >> 3, bNq = (tid & 7) * 16;

    const float* aPtr = A + (size_t)(row0 + aRow) * K + aKq;
    const float* bPtr = B + (size_t)bK * N + col0 + bNq;

    int KT = K / 16;

    #pragma unroll
    for (int s = 0; s < 3; s++) {
        if (s < KT) {
            cp16(&Asm[s][aRow][aKq], aPtr + s * 16);
            cp16(&Asm[s][aRow][aKq + 4], aPtr + s * 16 + 4);
            const float* bp = bPtr + (size_t)(s * 16) * N;
            cp16(&Bsm[s][bK][bNq],      bp);
            cp16(&Bsm[s][bK][bNq + 4],  bp + 4);
            cp16(&Bsm[s][bK][bNq + 8],  bp + 8);
            cp16(&Bsm[s][bK][bNq + 12], bp + 12);
        }
        CP_COMMIT();
    }

    for (int kt = 0; kt < KT; kt++) {
        CP_WAIT2();
        __syncthreads();

        {
            int s = kt + 3;
            int st2 = s & 3;
            if (s < KT) {
                cp16(&Asm[st2][aRow][aKq], aPtr + s * 16);
                cp16(&Asm[st2][aRow][aKq + 4], aPtr + s * 16 + 4);
                const float* bp = bPtr + (size_t)(s * 16) * N;
                cp16(&Bsm[st2][bK][bNq],      bp);
                cp16(&Bsm[st2][bK][bNq + 4],  bp + 4);
                cp16(&Bsm[st2][bK][bNq + 8],  bp + 8);
                cp16(&Bsm[st2][bK][bNq + 12], bp + 12);
            }
            CP_COMMIT();
        }

        int st = kt & 3;
        #pragma unroll
        for (int ks = 0; ks < 2; ks++) {
            // split A fragments
            unsigned int afH[2][4], afL[2][4];
            #pragma unroll
            for (int mt = 0; mt < 2; mt++) {
                int r = warpM * 32 + mt * 16 + gid;
                int c = ks * 8 + tig;
                split_tf32(Asm[st][r][c],         afH[mt][0], afL[mt][0]);
                split_tf32(Asm[st][r + 8][c],     afH[mt][1], afL[mt][1]);
                split_tf32(Asm[st][r][c + 4],     afH[mt][2], afL[mt][2]);
                split_tf32(Asm[st][r + 8][c + 4], afH[mt][3], afL[mt][3]);
            }
            // split ALL B fragments up-front
            unsigned int bfH[8][2], bfL[8][2];
            #pragma unroll
            for (int nt = 0; nt < 8; nt++) {
                int n = warpN * 64 + nt * 8 + gid;
                int kk = ks * 8 + tig;
                split_tf32(Bsm[st][kk][n],     bfH[nt][0], bfL[nt][0]);
                split_tf32(Bsm[st][kk + 4][n], bfH[nt][1], bfL[nt][1]);
            }
            // term-major issue: 16 independent mma between same-acc reuses
            #pragma unroll
            for (int nt = 0; nt < 8; nt++)
                #pragma unroll
                for (int mt = 0; mt < 2; mt++)
                    MMA_TF32(acc[mt][nt], afH[mt][0], afH[mt][1], afH[mt][2], afH[mt][3],
                             bfL[nt][0], bfL[nt][1]);
            #pragma unroll
            for (int nt = 0; nt < 8; nt++)
                #pragma unroll
                for (int mt = 0; mt < 2; mt++)
                    MMA_TF32(acc[mt][nt], afL[mt][0], afL[mt][1], afL[mt][2], afL[mt][3],
                             bfH[nt][0], bfH[nt][1]);
            #pragma unroll
            for (int nt = 0; nt < 8; nt++)
                #pragma unroll
                for (int mt = 0; mt < 2; mt++)
                    MMA_TF32(acc[mt][nt], afH[mt][0], afH[mt][1], afH[mt][2], afH[mt][3],
                             bfH[nt][0], bfH[nt][1]);
        }
    }

    // epilogue
    #pragma unroll
    for (int mt = 0; mt < 2; mt++) {
        int r = row0 + warpM * 32 + mt * 16 + gid;
        #pragma unroll
        for (int nt = 0; nt < 8; nt++) {
            int c = col0 + warpN * 64 + nt * 8 + tig * 2;
            float* p0 = C + (size_t)r * N + c;
            float* p1 = C + (size_t)(r + 8) * N + c;
            if (accum) {
                p0[0] += acc[mt][nt][0]; p0[1] += acc[mt][nt][1];
                p1[0] += acc[mt][nt][2]; p1[1] += acc[mt][nt][3];
            } else {
                p0[0] = acc[mt][nt][0]; p0[1] = acc[mt][nt][1];
                p1[0] = acc[mt][nt][2]; p1[1] = acc[mt][nt][3];
            }
        }
    }
}

__global__ __launch_bounds__(128, 3)
void tf32gemm_k(int M, int N, int K,
                const float* __restrict__ A, const float* __restrict__ B,
                float* __restrict__ C, int accum) {
    __shared__ float Asm[4][64][20];
    __shared__ float Bsm[4][16][136];
    gemm_core(M, N, K, A, B, C, accum,
              blockIdx.y * 64, blockIdx.x * 128, Asm, Bsm);
}

__global__ __launch_bounds__(128, 3)
void tf32gemm3_k(int M, int N, int K, const float* __restrict__ A,
                 const float* __restrict__ B0, const float* __restrict__ B1,
                 const float* __restrict__ B2,
                 float* __restrict__ C0, float* __restrict__ C1,
                 float* __restrict__ C2) {
    __shared__ float Asm[4][64][20];
    __shared__ float Bsm[4][16][136];
    const float* B = (blockIdx.z == 0) ? B0 : (blockIdx.z == 1) ? B1 : B2;
    float*       C = (blockIdx.z == 0) ? C0 : (blockIdx.z == 1) ? C1 : C2;
    gemm_core(M, N, K, A, B, C, 0,
              blockIdx.y * 64, blockIdx.x * 128, Asm, Bsm);
}

// ---------------- elementwise ----------------
__global__ void conv_silu3_k(const float* __restrict__ xq, const float* __restrict__ xk,
                             const float* __restrict__ xv,
                             const float* __restrict__ wq, const float* __restrict__ wk,
                             const float* __restrict__ wv,
                             float* __restrict__ yq, float* __restrict__ yk,
                             float* __restrict__ yv) {
    int z = blockIdx.y;
    const float* x = (z == 0) ? xq : (z == 1) ? xk : xv;
    const float* w = (z == 0) ? wq : (z == 1) ? wk : wv;
    float*       y = (z == 0) ? yq : (z == 1) ? yk : yv;
    int i = blockIdx.x * blockDim.x + threadIdx.x;
    if (i >= T_ * D_) return;
    int t = i / D_, d = i % D_;
    float s = 0.f;
    #pragma unroll
    for (int j = 0; j < KC; j++) {
        int tt = t + j - (KC - 1);
        if (tt >= 0) s += x[tt*D_ + d] * w[d*KC + j];
    }
    y[i] = s / (1.f + expf(-s));
}

__global__ void l2norm2_k(float* __restrict__ q, float* __restrict__ k) {
    float* x = (blockIdx.y == 0) ? q : k;
    int base = blockIdx.x * DK_;
    int tid = threadIdx.x;
    __shared__ float red[64];
    float v = x[base + tid];
    red[tid] = v * v; __syncthreads();
    for (int s = 32; s > 0; s >>= 1) {
        if (tid < s) red[tid] += red[tid + s];
        __syncthreads();
    }
    x[base + tid] = v * rsqrtf(red[0] + EPSF);
}

__global__ void headrms_k(float* __restrict__ x, const float* __restrict__ w) {
    int base = blockIdx.x * DK_;
    int tid = threadIdx.x;
    __shared__ float red[64];
    float v = x[base + tid];
    red[tid] = v * v; __syncthreads();
    for (int s = 32; s > 0; s >>= 1) {
        if (tid < s) red[tid] += red[tid + s];
        __syncthreads();
    }
    x[base + tid] = v * rsqrtf(red[0] / DK_ + EPSF) * w[tid];
}

__global__ void silu_mul_k(float* __restrict__ g, const float* __restrict__ u, int n) {
    int i = blockIdx.x * blockDim.x + threadIdx.x;
    if (i < n) { float v = g[i]; g[i] = (v / (1.f + expf(-v))) * u[i]; }
}

// ---------------- delta rule (128 threads — proven layout) ----------
__global__ void delta_k(const float* __restrict__ q, const float* __restrict__ k,
                        const float* __restrict__ v, const float* __restrict__ beta,
                        float* __restrict__ o) {
    int h = blockIdx.x;
    int tid = threadIdx.x;
    int vcol = tid >> 1, rbase = (tid & 1) * 32;
    float S[32];
    #pragma unroll
    for (int i = 0; i < 32; i++) S[i] = 0.f;
    __shared__ float ks[2][64], qs[2][64], vs[2][64], bsh[2];

    float rk = 0.f, rq = 0.f, rv = 0.f, rb = 0.f;
    {
        int off = h * DK_;
        if (tid < 64) { rk = k[off + tid]; rq = q[off + tid]; }
        else          { rv = v[off + tid - 64]; }
        if (tid == 127) rb = beta[h];
    }

    for (int t = 0; t < T_; t++) {
        int buf = t & 1;
        if (tid < 64) { ks[buf][tid] = rk; qs[buf][tid] = rq; }
        else          { vs[buf][tid - 64] = rv; }
        if (tid == 127) bsh[buf] = rb;
        __syncthreads();

        if (t + 1 < T_) {
            int off2 = ((t + 1) * H_ + h) * DK_;
            if (tid < 64) { rk = k[off2 + tid]; rq = q[off2 + tid]; }
            else          { rv = v[off2 + tid - 64]; }
            if (tid == 127) rb = beta[(t + 1) * H_ + h];
        }

        const float* kk = ks[buf];
        const float* qq = qs[buf];
        float a0 = 0.f, a1 = 0.f;
        #pragma unroll
        for (int i = 0; i < 32; i += 2) {
            a0 += kk[rbase+i]   * S[i];
            a1 += kk[rbase+i+1] * S[i+1];
        }
        float part = a0 + a1;
        float kS = part + __shfl_xor_sync(0xffffffffu, part, 1);
        float dl = bsh[buf] * (vs[buf][vcol] - kS);

        float o0 = 0.f, o1 = 0.f;
        #pragma unroll
        for (int i = 0; i < 32; i += 2) {
            S[i]   += kk[rbase+i]   * dl;  o0 += qq[rbase+i]   * S[i];
            S[i+1] += kk[rbase+i+1] * dl;  o1 += qq[rbase+i+1] * S[i+1];
        }
        float op = o0 + o1;
        float ov = op + __shfl_xor_sync(0xffffffffu, op, 1);
        int off = (t * H_ + h) * DK_;
        if ((tid & 1) == 0) o[off + vcol] = ov;
    }
}

__global__ void zero_loss_k() { g_loss = 0.f; g_cnt = 0.f; }

__global__ void loss_k(const float* __restrict__ logits, const int* __restrict__ tgt) {
    int t = blockIdx.x;
    const float* row = logits + (size_t)t * V_;
    __shared__ float red[256];
    float m = -1e30f;
    for (int i = threadIdx.x; i < V_; i += 256) m = fmaxf(m, row[i]);
    red[threadIdx.x] = m; __syncthreads();
    for (int s = 128; s > 0; s >>= 1) {
        if (threadIdx.x < s) red[threadIdx.x] = fmaxf(red[threadIdx.x], red[threadIdx.x+s]);
        __syncthreads();
    }
    m = red[0]; __syncthreads();
    float sum = 0.f;
    for (int i = threadIdx.x; i < V_; i += 256) sum += expf(row[i] - m);
    red[threadIdx.x] = sum; __syncthreads();
    for (int s = 128; s > 0; s >>= 1) {
        if (threadIdx.x < s) red[threadIdx.x] += red[threadIdx.x+s];
        __syncthreads();
    }
    if (threadIdx.x == 0) {
        int tg = tgt[t];
        if (tg >= 0) {
            int tc = tg < 0 ? 0 : (tg > V_-1 ? V_-1 : tg);
            float lse = m + logf(red[0]);
            atomicAdd(&g_loss, lse - row[tc]);
            atomicAdd(&g_cnt, 1.f);
        }
    }
}

__global__ void finalize_k(float* __restrict__ out, long long out_size) {
    float loss = g_loss / fmaxf(g_cnt, 1.f);
    const long long LG = (long long)T_ * V_;
    if (out_size == LG + 1) out[LG] = loss;
    else if (out_size < LG) out[0] = loss;
}

// ---------------- host side ----------------
static void run_gemm(int M, int N, int K, const float* A, const float* B, float* C, int accum) {
    dim3 grid(N / 128, M / 64);
    tf32gemm_k<<<grid, 128>>>(M, N, K, A, B, C, accum);
}

static void run_gemm_multi(int M, int N, int K, const float* A,
                           const float* B0, const float* B1, const float* B2,
                           float* C0, float* C1, float* C2, int nmat) {
    dim3 grid(N / 128, M / 64, nmat);
    tf32gemm3_k<<<grid, 128>>>(M, N, K, A, B0, B1, B2, C0, C1, C2);
}

extern "C" void kernel_launch(void* const* d_in, const int* in_sizes, int n_in,
                              void* d_out, int out_size) {
    const int*   idx        = (const int*)  d_in[0];
    const int*   targets    = (const int*)  d_in[1];
    const float* embed      = (const float*)d_in[2];
    const float* Wq         = (const float*)d_in[3];
    const float* Wk         = (const float*)d_in[4];
    const float* Wv         = (const float*)d_in[5];
    const float* conv_q     = (const float*)d_in[6];
    const float* conv_k     = (const float*)d_in[7];
    const float* conv_v     = (const float*)d_in[8];
    const float* Wb         = (const float*)d_in[9];
    const float* o_norm_w   = (const float*)d_in[10];
    const float* Wo         = (const float*)d_in[11];
    const float* attn_norm  = (const float*)d_in[12];
    const float* mlp_norm   = (const float*)d_in[13];
    const float* Wgate      = (const float*)d_in[14];
    const float* Wup        = (const float*)d_in[15];
    const float* Wdown      = (const float*)d_in[16];
    const float* final_norm = (const float*)d_in[17];
    const float* lm_head    = (const float*)d_in[18];

    float *h, *x, *qp, *kp, *vp, *q, *k, *v, *o, *y, *gate, *up, *beta, *lfb;
    cudaGetSymbolAddress((void**)&h,    g_h);
    cudaGetSymbolAddress((void**)&x,    g_x);
    cudaGetSymbolAddress((void**)&qp,   g_qp);
    cudaGetSymbolAddress((void**)&kp,   g_kp);
    cudaGetSymbolAddress((void**)&vp,   g_vp);
    cudaGetSymbolAddress((void**)&q,    g_q);
    cudaGetSymbolAddress((void**)&k,    g_k);
    cudaGetSymbolAddress((void**)&v,    g_v);
    cudaGetSymbolAddress((void**)&o,    g_o);
    cudaGetSymbolAddress((void**)&y,    g_y);
    cudaGetSymbolAddress((void**)&gate, g_gate);
    cudaGetSymbolAddress((void**)&up,   g_up);
    cudaGetSymbolAddress((void**)&beta, g_beta);
    cudaGetSymbolAddress((void**)&lfb,  g_logits_fb);

    const long long LG = (long long)T_ * V_;
    float* logits = ((long long)out_size >= LG) ? (float*)d_out : lfb;

    const int TD = T_ * D_;
    const int TF = T_ * FF_;

    embed_k<<<(TD + 255) / 256, 256>>>(idx, embed, h);

    for (int l = 0; l < L_; l++) {
        const float* Wq_l = Wq + (size_t)l * D_ * D_;
        const float* Wk_l = Wk + (size_t)l * D_ * D_;
        const float* Wv_l = Wv + (size_t)l * D_ * D_;
        const float* Wo_l = Wo + (size_t)l * D_ * D_;
        const float* Wb_l = Wb + (size_t)l * D_ * H_;
        const float* cq_l = conv_q + (size_t)l * D_ * KC;
        const float* ck_l = conv_k + (size_t)l * D_ * KC;
        const float* cv_l = conv_v + (size_t)l * D_ * KC;
        const float* Wg_l = Wgate + (size_t)l * D_ * FF_;
        const float* Wu_l = Wup   + (size_t)l * D_ * FF_;
        const float* Wd_l = Wdown + (size_t)l * FF_ * D_;

        rmsnorm_k<<<T_, 256>>>(h, attn_norm + (size_t)l * D_, x);

        run_gemm_multi(T_, D_, D_, x, Wq_l, Wk_l, Wv_l, qp, kp, vp, 3);
        beta_k<<<T_ / 8, 256>>>(x, Wb_l, beta);

        {
            dim3 grid((TD + 255) / 256, 3);
            conv_silu3_k<<<grid, 256>>>(qp, kp, vp, cq_l, ck_l, cv_l, q, k, v);
        }
        {
            dim3 grid(T_ * H_, 2);
            l2norm2_k<<<grid, 64>>>(q, k);
        }

        delta_k<<<H_, 128>>>(q, k, v, beta, o);

        headrms_k<<<T_*H_, 64>>>(o, o_norm_w + (size_t)l * DK_);

        run_gemm(T_, D_, D_, o, Wo_l, h, 1);

        rmsnorm_k<<<T_, 256>>>(h, mlp_norm + (size_t)l * D_, y);
        run_gemm_multi(T_, FF_, D_, y, Wg_l, Wu_l, Wu_l, gate, up, up, 2);
        silu_mul_k<<<(TF + 255) / 256, 256>>>(gate, up, TF);
        run_gemm(T_, D_, FF_, gate, Wd_l, h, 1);
    }

    rmsnorm_k<<<T_, 256>>>(h, final_norm, y);
    run_gemm(T_, V_, D_, y, lm_head, logits, 0);

    zero_loss_k<<<1, 1>>>();
    loss_k<<<T_, 256>>>(logits, targets);
    finalize_k<<<1, 1>>>((float*)d_out, (long long)out_size);
}

// round 17
// speedup vs baseline: 1.2362x; 1.2362x over previous
#include <cuda_runtime.h>
#include <cuda_fp16.h>
#include <stdint.h>
#include <math.h>

#define T_  2048
#define D_  768
#define L_  12
#define H_  12
#define DK_ 64
#define FF_ 2048
#define V_  50304
#define KC  4
#define EPSF 1e-6f

// ---------------- scratch (device globals; no runtime allocation) ----------------
__device__ float g_h  [T_*D_];
__device__ float g_x  [T_*D_];
__device__ float g_qp [T_*D_];
__device__ float g_kp [T_*D_];
__device__ float g_vp [T_*D_];
__device__ float g_q  [T_*D_];
__device__ float g_k  [T_*D_];
__device__ float g_v  [T_*D_];
__device__ float g_o  [T_*D_];
__device__ float g_y  [T_*D_];
__device__ float g_gate[T_*FF_];
__device__ float g_up  [T_*FF_];
__device__ float g_beta[T_*H_];
__device__ float g_loss, g_cnt;
__device__ float g_logits_fb[(size_t)T_*V_];

// packed-fp16 split planes (u32 = 2 halves along k)
#define WQK_SZ  (12 * 384 * 768)      // Wq/Wk/Wv/Wo per-plane u32 count
#define WGU_SZ  (12 * 384 * 2048)     // Wgate/Wup
#define WDN_SZ  (12 * 1024 * 768)     // Wdown
#define WLM_SZ  (384 * 50304)         // lm_head
__device__ uint32_t g_Wqh[WQK_SZ], g_Wql[WQK_SZ];
__device__ uint32_t g_Wkh[WQK_SZ], g_Wkl[WQK_SZ];
__device__ uint32_t g_Wvh[WQK_SZ], g_Wvl[WQK_SZ];
__device__ uint32_t g_Woh[WQK_SZ], g_Wol[WQK_SZ];
__device__ uint32_t g_Wgh[WGU_SZ], g_Wgl[WGU_SZ];
__device__ uint32_t g_Wuh[WGU_SZ], g_Wul[WGU_SZ];
__device__ uint32_t g_Wdh[WDN_SZ], g_Wdl[WDN_SZ];
__device__ uint32_t g_LMh[WLM_SZ], g_LMl[WLM_SZ];
__device__ uint32_t g_Aah[T_*FF_/2], g_Aal[T_*FF_/2];   // activation planes (max gate)

// ---------------- small kernels ----------------
__global__ void embed_k(const int* __restrict__ idx, const float* __restrict__ embed,
                        float* __restrict__ h) {
    int i = blockIdx.x * blockDim.x + threadIdx.x;
    if (i < T_ * D_) {
        int t = i / D_, d = i % D_;
        h[i] = embed[(size_t)idx[t] * D_ + d];
    }
}

__global__ void rmsnorm_k(const float* __restrict__ x, const float* __restrict__ w,
                          float* __restrict__ y) {
    int t = blockIdx.x;
    __shared__ float red[256];
    float ss = 0.f;
    for (int d = threadIdx.x; d < D_; d += 256) { float v = x[t*D_+d]; ss += v*v; }
    red[threadIdx.x] = ss; __syncthreads();
    for (int s = 128; s > 0; s >>= 1) {
        if (threadIdx.x < s) red[threadIdx.x] += red[threadIdx.x + s];
        __syncthreads();
    }
    float r = rsqrtf(red[0] / D_ + EPSF);
    for (int d = threadIdx.x; d < D_; d += 256) y[t*D_+d] = x[t*D_+d] * r * w[d];
}

__global__ __launch_bounds__(256)
void beta_k(const float* __restrict__ x, const float* __restrict__ Wb,
            float* __restrict__ beta) {
    int warp = threadIdx.x >> 5, lane = threadIdx.x & 31;
    int t = blockIdx.x * 8 + warp;
    if (t >= T_) return;
    float xv[24];
    #pragma unroll
    for (int j = 0; j < 24; j++) xv[j] = x[t * D_ + lane + 32 * j];
    #pragma unroll
    for (int h = 0; h < H_; h++) {
        float acc = 0.f;
        #pragma unroll
        for (int j = 0; j < 24; j++) acc += xv[j] * Wb[(lane + 32 * j) * H_ + h];
        #pragma unroll
        for (int s = 16; s > 0; s >>= 1) acc += __shfl_xor_sync(0xffffffffu, acc, s);
        if (lane == 0) beta[t * H_ + h] = 1.f / (1.f + expf(-acc));
    }
}

// ---------------- fp16 split pre-pass ----------------
__device__ __forceinline__ void split_h(float f, unsigned short& h, unsigned short& l) {
    __half hh = __float2half_rn(f);
    float r = f - __half2float(hh);
    __half ll = __float2half_rn(r);
    h = __half_as_ushort(hh);
    l = __half_as_ushort(ll);
}

// A: row-major [M][K], pairs are contiguous: pair i = elements 2i, 2i+1
__global__ void splitA_k(const float* __restrict__ A, uint32_t* __restrict__ h,
                         uint32_t* __restrict__ l, int npairs) {
    int i = blockIdx.x * blockDim.x + threadIdx.x;
    if (i >= npairs) return;
    float f0 = A[2*i], f1 = A[2*i + 1];
    unsigned short h0, l0, h1, l1;
    split_h(f0, h0, l0); split_h(f1, h1, l1);
    h[i] = (uint32_t)h0 | ((uint32_t)h1 << 16);
    l[i] = (uint32_t)l0 | ((uint32_t)l1 << 16);
}

// B: [K][N] row-major -> packed [K/2][N] u32 (pair along k)
__global__ void splitB_k(const float* __restrict__ B, uint32_t* __restrict__ h,
                         uint32_t* __restrict__ l, int Kp, int N) {
    int i = blockIdx.x * blockDim.x + threadIdx.x;
    if (i >= Kp * N) return;
    int kp = i / N, n = i - kp * N;
    float f0 = B[(size_t)(2*kp) * N + n];
    float f1 = B[(size_t)(2*kp + 1) * N + n];
    unsigned short h0, l0, h1, l1;
    split_h(f0, h0, l0); split_h(f1, h1, l1);
    h[i] = (uint32_t)h0 | ((uint32_t)h1 << 16);
    l[i] = (uint32_t)l0 | ((uint32_t)l1 << 16);
}

// ---------------- split-fp16 tensor-core GEMM, 4-stage cp.async pipeline -----
// C[M,N] = A[M,K] @ B[K,N] (+C). Operands pre-split into packed fp16 planes.
// CTA tile 64x128, k-chunk 16 (8 kp); 128 threads = 4 warps (2Mx2N), warp 32x64.
__device__ __forceinline__ void cp16(void* smem, const void* gmem) {
    unsigned int sa = (unsigned int)__cvta_generic_to_shared(smem);
    asm volatile("cp.async.ca.shared.global [%0], [%1], 16;" :: "r"(sa), "l"(gmem));
}
#define CP_COMMIT() asm volatile("cp.async.commit_group;")
#define CP_WAIT2()  asm volatile("cp.async.wait_group 2;")

#define MMA_F16(acc, a0,a1,a2,a3, b0,b1)                                      \
    asm volatile(                                                             \
        "mma.sync.aligned.m16n8k16.row.col.f32.f16.f16.f32 "                  \
        "{%0,%1,%2,%3}, {%4,%5,%6,%7}, {%8,%9}, {%0,%1,%2,%3};\n"             \
        : "+f"(acc[0]), "+f"(acc[1]), "+f"(acc[2]), "+f"(acc[3])              \
        : "r"(a0), "r"(a1), "r"(a2), "r"(a3), "r"(b0), "r"(b1))

__device__ __forceinline__
void hgemm_core(int M, int N, int Kp,
                const uint32_t* __restrict__ Ah, const uint32_t* __restrict__ Al,
                const uint32_t* __restrict__ Bh, const uint32_t* __restrict__ Bl,
                float* __restrict__ C, int accum, int row0, int col0,
                uint32_t (*AsH)[64][12], uint32_t (*AsL)[64][12],
                uint32_t (*BsH)[8][136], uint32_t (*BsL)[8][136]) {
    int tid = threadIdx.x;
    int lane = tid & 31, warp = tid >> 5;
    int warpM = warp & 1, warpN = warp >> 1;
    int gid = lane >> 2, tig = lane & 3;

    float acc[2][8][4];
    #pragma unroll
    for (int mt = 0; mt < 2; mt++)
        #pragma unroll
        for (int nt = 0; nt < 8; nt++)
            #pragma unroll
            for (int i = 0; i < 4; i++) acc[mt][nt][i] = 0.f;

    // A loader: 64 rows x 8 u32; thread: row=tid/2, kq=(tid&1)*4 -> 1 cp16/plane
    int aRow = tid >> 1, aKq = (tid & 1) * 4;
    // B loader: 8 kp x 128 n; thread: kp=tid/16, nq=(tid&15)*8 -> 2 cp16/plane
    int bKp = tid >> 4, bNq = (tid & 15) * 8;

    const uint32_t* ahp = Ah + (size_t)(row0 + aRow) * Kp + aKq;
    const uint32_t* alp = Al + (size_t)(row0 + aRow) * Kp + aKq;
    const uint32_t* bhp = Bh + (size_t)bKp * N + col0 + bNq;
    const uint32_t* blp = Bl + (size_t)bKp * N + col0 + bNq;

    int KT = Kp / 8;

    #pragma unroll
    for (int s = 0; s < 3; s++) {
        if (s < KT) {
            cp16(&AsH[s][aRow][aKq], ahp + s * 8);
            cp16(&AsL[s][aRow][aKq], alp + s * 8);
            size_t bo = (size_t)s * 8 * N;
            cp16(&BsH[s][bKp][bNq],     bhp + bo);
            cp16(&BsH[s][bKp][bNq + 4], bhp + bo + 4);
            cp16(&BsL[s][bKp][bNq],     blp + bo);
            cp16(&BsL[s][bKp][bNq + 4], blp + bo + 4);
        }
        CP_COMMIT();
    }

    for (int kt = 0; kt < KT; kt++) {
        CP_WAIT2();
        __syncthreads();

        {
            int s = kt + 3;
            int st2 = s & 3;
            if (s < KT) {
                cp16(&AsH[st2][aRow][aKq], ahp + s * 8);
                cp16(&AsL[st2][aRow][aKq], alp + s * 8);
                size_t bo = (size_t)s * 8 * N;
                cp16(&BsH[st2][bKp][bNq],     bhp + bo);
                cp16(&BsH[st2][bKp][bNq + 4], bhp + bo + 4);
                cp16(&BsL[st2][bKp][bNq],     blp + bo);
                cp16(&BsL[st2][bKp][bNq + 4], blp + bo + 4);
            }
            CP_COMMIT();
        }

        int st = kt & 3;
        // A fragments (m16n8k16: a0,a1 = kp tig; a2,a3 = kp tig+4)
        unsigned int aH[2][4], aL[2][4];
        #pragma unroll
        for (int mt = 0; mt < 2; mt++) {
            int r = warpM * 32 + mt * 16 + gid;
            aH[mt][0] = AsH[st][r][tig];     aL[mt][0] = AsL[st][r][tig];
            aH[mt][1] = AsH[st][r + 8][tig]; aL[mt][1] = AsL[st][r + 8][tig];
            aH[mt][2] = AsH[st][r][tig + 4]; aL[mt][2] = AsL[st][r][tig + 4];
            aH[mt][3] = AsH[st][r + 8][tig + 4]; aL[mt][3] = AsL[st][r + 8][tig + 4];
        }
        #pragma unroll
        for (int nt = 0; nt < 8; nt++) {
            int n = warpN * 64 + nt * 8 + gid;
            unsigned int bH0 = BsH[st][tig][n],     bL0 = BsL[st][tig][n];
            unsigned int bH1 = BsH[st][tig + 4][n], bL1 = BsL[st][tig + 4][n];
            #pragma unroll
            for (int mt = 0; mt < 2; mt++) {
                MMA_F16(acc[mt][nt], aH[mt][0], aH[mt][1], aH[mt][2], aH[mt][3], bL0, bL1);
                MMA_F16(acc[mt][nt], aL[mt][0], aL[mt][1], aL[mt][2], aL[mt][3], bH0, bH1);
                MMA_F16(acc[mt][nt], aH[mt][0], aH[mt][1], aH[mt][2], aH[mt][3], bH0, bH1);
            }
        }
    }

    #pragma unroll
    for (int mt = 0; mt < 2; mt++) {
        int r = row0 + warpM * 32 + mt * 16 + gid;
        #pragma unroll
        for (int nt = 0; nt < 8; nt++) {
            int c = col0 + warpN * 64 + nt * 8 + tig * 2;
            float* p0 = C + (size_t)r * N + c;
            float* p1 = C + (size_t)(r + 8) * N + c;
            if (accum) {
                p0[0] += acc[mt][nt][0]; p0[1] += acc[mt][nt][1];
                p1[0] += acc[mt][nt][2]; p1[1] += acc[mt][nt][3];
            } else {
                p0[0] = acc[mt][nt][0]; p0[1] = acc[mt][nt][1];
                p1[0] = acc[mt][nt][2]; p1[1] = acc[mt][nt][3];
            }
        }
    }
}

__global__ __launch_bounds__(128, 3)
void hgemm_k(int M, int N, int Kp,
             const uint32_t* __restrict__ Ah, const uint32_t* __restrict__ Al,
             const uint32_t* __restrict__ Bh, const uint32_t* __restrict__ Bl,
             float* __restrict__ C, int accum) {
    __shared__ uint32_t AsH[4][64][12], AsL[4][64][12];
    __shared__ uint32_t BsH[4][8][136], BsL[4][8][136];
    hgemm_core(M, N, Kp, Ah, Al, Bh, Bl, C, accum,
               blockIdx.y * 64, blockIdx.x * 128, AsH, AsL, BsH, BsL);
}

__global__ __launch_bounds__(128, 3)
void hgemm3_k(int M, int N, int Kp,
              const uint32_t* __restrict__ Ah, const uint32_t* __restrict__ Al,
              const uint32_t* __restrict__ B0h, const uint32_t* __restrict__ B0l,
              const uint32_t* __restrict__ B1h, const uint32_t* __restrict__ B1l,
              const uint32_t* __restrict__ B2h, const uint32_t* __restrict__ B2l,
              float* __restrict__ C0, float* __restrict__ C1, float* __restrict__ C2) {
    __shared__ uint32_t AsH[4][64][12], AsL[4][64][12];
    __shared__ uint32_t BsH[4][8][136], BsL[4][8][136];
    const uint32_t* Bh = (blockIdx.z == 0) ? B0h : (blockIdx.z == 1) ? B1h : B2h;
    const uint32_t* Bl = (blockIdx.z == 0) ? B0l : (blockIdx.z == 1) ? B1l : B2l;
    float*          C  = (blockIdx.z == 0) ? C0  : (blockIdx.z == 1) ? C1  : C2;
    hgemm_core(M, N, Kp, Ah, Al, Bh, Bl, C, 0,
               blockIdx.y * 64, blockIdx.x * 128, AsH, AsL, BsH, BsL);
}

// ---------------- elementwise ----------------
__global__ void conv_silu3_k(const float* __restrict__ xq, const float* __restrict__ xk,
                             const float* __restrict__ xv,
                             const float* __restrict__ wq, const float* __restrict__ wk,
                             const float* __restrict__ wv,
                             float* __restrict__ yq, float* __restrict__ yk,
                             float* __restrict__ yv) {
    int z = blockIdx.y;
    const float* x = (z == 0) ? xq : (z == 1) ? xk : xv;
    const float* w = (z == 0) ? wq : (z == 1) ? wk : wv;
    float*       y = (z == 0) ? yq : (z == 1) ? yk : yv;
    int i = blockIdx.x * blockDim.x + threadIdx.x;
    if (i >= T_ * D_) return;
    int t = i / D_, d = i % D_;
    float s = 0.f;
    #pragma unroll
    for (int j = 0; j < KC; j++) {
        int tt = t + j - (KC - 1);
        if (tt >= 0) s += x[tt*D_ + d] * w[d*KC + j];
    }
    y[i] = s / (1.f + expf(-s));
}

__global__ void l2norm2_k(float* __restrict__ q, float* __restrict__ k) {
    float* x = (blockIdx.y == 0) ? q : k;
    int base = blockIdx.x * DK_;
    int tid = threadIdx.x;
    __shared__ float red[64];
    float v = x[base + tid];
    red[tid] = v * v; __syncthreads();
    for (int s = 32; s > 0; s >>= 1) {
        if (tid < s) red[tid] += red[tid + s];
        __syncthreads();
    }
    x[base + tid] = v * rsqrtf(red[0] + EPSF);
}

__global__ void headrms_k(float* __restrict__ x, const float* __restrict__ w) {
    int base = blockIdx.x * DK_;
    int tid = threadIdx.x;
    __shared__ float red[64];
    float v = x[base + tid];
    red[tid] = v * v; __syncthreads();
    for (int s = 32; s > 0; s >>= 1) {
        if (tid < s) red[tid] += red[tid + s];
        __syncthreads();
    }
    x[base + tid] = v * rsqrtf(red[0] / DK_ + EPSF) * w[tid];
}

__global__ void silu_mul_k(float* __restrict__ g, const float* __restrict__ u, int n) {
    int i = blockIdx.x * blockDim.x + threadIdx.x;
    if (i < n) { float v = g[i]; g[i] = (v / (1.f + expf(-v))) * u[i]; }
}

// ---------------- delta rule (128 threads — proven layout) ----------
__global__ void delta_k(const float* __restrict__ q, const float* __restrict__ k,
                        const float* __restrict__ v, const float* __restrict__ beta,
                        float* __restrict__ o) {
    int h = blockIdx.x;
    int tid = threadIdx.x;
    int vcol = tid >> 1, rbase = (tid & 1) * 32;
    float S[32];
    #pragma unroll
    for (int i = 0; i < 32; i++) S[i] = 0.f;
    __shared__ float ks[2][64], qs[2][64], vs[2][64], bsh[2];

    float rk = 0.f, rq = 0.f, rv = 0.f, rb = 0.f;
    {
        int off = h * DK_;
        if (tid < 64) { rk = k[off + tid]; rq = q[off + tid]; }
        else          { rv = v[off + tid - 64]; }
        if (tid == 127) rb = beta[h];
    }

    for (int t = 0; t < T_; t++) {
        int buf = t & 1;
        if (tid < 64) { ks[buf][tid] = rk; qs[buf][tid] = rq; }
        else          { vs[buf][tid - 64] = rv; }
        if (tid == 127) bsh[buf] = rb;
        __syncthreads();

        if (t + 1 < T_) {
            int off2 = ((t + 1) * H_ + h) * DK_;
            if (tid < 64) { rk = k[off2 + tid]; rq = q[off2 + tid]; }
            else          { rv = v[off2 + tid - 64]; }
            if (tid == 127) rb = beta[(t + 1) * H_ + h];
        }

        const float* kk = ks[buf];
        const float* qq = qs[buf];
        float a0 = 0.f, a1 = 0.f;
        #pragma unroll
        for (int i = 0; i < 32; i += 2) {
            a0 += kk[rbase+i]   * S[i];
            a1 += kk[rbase+i+1] * S[i+1];
        }
        float part = a0 + a1;
        float kS = part + __shfl_xor_sync(0xffffffffu, part, 1);
        float dl = bsh[buf] * (vs[buf][vcol] - kS);

        float o0 = 0.f, o1 = 0.f;
        #pragma unroll
        for (int i = 0; i < 32; i += 2) {
            S[i]   += kk[rbase+i]   * dl;  o0 += qq[rbase+i]   * S[i];
            S[i+1] += kk[rbase+i+1] * dl;  o1 += qq[rbase+i+1] * S[i+1];
        }
        float op = o0 + o1;
        float ov = op + __shfl_xor_sync(0xffffffffu, op, 1);
        int off = (t * H_ + h) * DK_;
        if ((tid & 1) == 0) o[off + vcol] = ov;
    }
}

__global__ void zero_loss_k() { g_loss = 0.f; g_cnt = 0.f; }

__global__ void loss_k(const float* __restrict__ logits, const int* __restrict__ tgt) {
    int t = blockIdx.x;
    const float* row = logits + (size_t)t * V_;
    __shared__ float red[256];
    float m = -1e30f;
    for (int i = threadIdx.x; i < V_; i += 256) m = fmaxf(m, row[i]);
    red[threadIdx.x] = m; __syncthreads();
    for (int s = 128; s > 0; s >>= 1) {
        if (threadIdx.x < s) red[threadIdx.x] = fmaxf(red[threadIdx.x], red[threadIdx.x+s]);
        __syncthreads();
    }
    m = red[0]; __syncthreads();
    float sum = 0.f;
    for (int i = threadIdx.x; i < V_; i += 256) sum += expf(row[i] - m);
    red[threadIdx.x] = sum; __syncthreads();
    for (int s = 128; s > 0; s >>= 1) {
        if (threadIdx.x < s) red[threadIdx.x] += red[threadIdx.x+s];
        __syncthreads();
    }
    if (threadIdx.x == 0) {
        int tg = tgt[t];
        if (tg >= 0) {
            int tc = tg < 0 ? 0 : (tg > V_-1 ? V_-1 : tg);
            float lse = m + logf(red[0]);
            atomicAdd(&g_loss, lse - row[tc]);
            atomicAdd(&g_cnt, 1.f);
        }
    }
}

__global__ void finalize_k(float* __restrict__ out, long long out_size) {
    float loss = g_loss / fmaxf(g_cnt, 1.f);
    const long long LG = (long long)T_ * V_;
    if (out_size == LG + 1) out[LG] = loss;
    else if (out_size < LG) out[0] = loss;
}

// ---------------- host side ----------------
static void run_splitA(const float* A, uint32_t* h, uint32_t* l, int npairs) {
    splitA_k<<<(npairs + 255) / 256, 256>>>(A, h, l, npairs);
}
static void run_splitB(const float* B, uint32_t* h, uint32_t* l, int Kp, int N) {
    int tot = Kp * N;
    splitB_k<<<(tot + 255) / 256, 256>>>(B, h, l, Kp, N);
}
static void run_hgemm(int M, int N, int Kp,
                      const uint32_t* Ah, const uint32_t* Al,
                      const uint32_t* Bh, const uint32_t* Bl, float* C, int accum) {
    dim3 grid(N / 128, M / 64);
    hgemm_k<<<grid, 128>>>(M, N, Kp, Ah, Al, Bh, Bl, C, accum);
}

extern "C" void kernel_launch(void* const* d_in, const int* in_sizes, int n_in,
                              void* d_out, int out_size) {
    const int*   idx        = (const int*)  d_in[0];
    const int*   targets    = (const int*)  d_in[1];
    const float* embed      = (const float*)d_in[2];
    const float* Wq         = (const float*)d_in[3];
    const float* Wk         = (const float*)d_in[4];
    const float* Wv         = (const float*)d_in[5];
    const float* conv_q     = (const float*)d_in[6];
    const float* conv_k     = (const float*)d_in[7];
    const float* conv_v     = (const float*)d_in[8];
    const float* Wb         = (const float*)d_in[9];
    const float* o_norm_w   = (const float*)d_in[10];
    const float* Wo         = (const float*)d_in[11];
    const float* attn_norm  = (const float*)d_in[12];
    const float* mlp_norm   = (const float*)d_in[13];
    const float* Wgate      = (const float*)d_in[14];
    const float* Wup        = (const float*)d_in[15];
    const float* Wdown      = (const float*)d_in[16];
    const float* final_norm = (const float*)d_in[17];
    const float* lm_head    = (const float*)d_in[18];

    float *h, *x, *qp, *kp, *vp, *q, *k, *v, *o, *y, *gate, *up, *beta, *lfb;
    cudaGetSymbolAddress((void**)&h,    g_h);
    cudaGetSymbolAddress((void**)&x,    g_x);
    cudaGetSymbolAddress((void**)&qp,   g_qp);
    cudaGetSymbolAddress((void**)&kp,   g_kp);
    cudaGetSymbolAddress((void**)&vp,   g_vp);
    cudaGetSymbolAddress((void**)&q,    g_q);
    cudaGetSymbolAddress((void**)&k,    g_k);
    cudaGetSymbolAddress((void**)&v,    g_v);
    cudaGetSymbolAddress((void**)&o,    g_o);
    cudaGetSymbolAddress((void**)&y,    g_y);
    cudaGetSymbolAddress((void**)&gate, g_gate);
    cudaGetSymbolAddress((void**)&up,   g_up);
    cudaGetSymbolAddress((void**)&beta, g_beta);
    cudaGetSymbolAddress((void**)&lfb,  g_logits_fb);

    uint32_t *Wqh, *Wql, *Wkh, *Wkl, *Wvh, *Wvl, *Woh, *Wol;
    uint32_t *Wgh, *Wgl, *Wuh, *Wul, *Wdh, *Wdl, *LMh, *LMl, *Aah, *Aal;
    cudaGetSymbolAddress((void**)&Wqh, g_Wqh); cudaGetSymbolAddress((void**)&Wql, g_Wql);
    cudaGetSymbolAddress((void**)&Wkh, g_Wkh); cudaGetSymbolAddress((void**)&Wkl, g_Wkl);
    cudaGetSymbolAddress((void**)&Wvh, g_Wvh); cudaGetSymbolAddress((void**)&Wvl, g_Wvl);
    cudaGetSymbolAddress((void**)&Woh, g_Woh); cudaGetSymbolAddress((void**)&Wol, g_Wol);
    cudaGetSymbolAddress((void**)&Wgh, g_Wgh); cudaGetSymbolAddress((void**)&Wgl, g_Wgl);
    cudaGetSymbolAddress((void**)&Wuh, g_Wuh); cudaGetSymbolAddress((void**)&Wul, g_Wul);
    cudaGetSymbolAddress((void**)&Wdh, g_Wdh); cudaGetSymbolAddress((void**)&Wdl, g_Wdl);
    cudaGetSymbolAddress((void**)&LMh, g_LMh); cudaGetSymbolAddress((void**)&LMl, g_LMl);
    cudaGetSymbolAddress((void**)&Aah, g_Aah); cudaGetSymbolAddress((void**)&Aal, g_Aal);

    const long long LG = (long long)T_ * V_;
    float* logits = ((long long)out_size >= LG) ? (float*)d_out : lfb;

    const int TD = T_ * D_;
    const int TF = T_ * FF_;
    const int KpD = D_ / 2;     // 384
    const int KpF = FF_ / 2;    // 1024

    embed_k<<<(TD + 255) / 256, 256>>>(idx, embed, h);

    // ---- one-shot weight splits (all layers as one tall matrix; 768/2048 even) ----
    run_splitB(Wq,      Wqh, Wql, L_ * KpD, D_);
    run_splitB(Wk,      Wkh, Wkl, L_ * KpD, D_);
    run_splitB(Wv,      Wvh, Wvl, L_ * KpD, D_);
    run_splitB(Wo,      Woh, Wol, L_ * KpD, D_);
    run_splitB(Wgate,   Wgh, Wgl, L_ * KpD, FF_);
    run_splitB(Wup,     Wuh, Wul, L_ * KpD, FF_);
    run_splitB(Wdown,   Wdh, Wdl, L_ * KpF, D_);
    run_splitB(lm_head, LMh, LMl, KpD, V_);

    const int WQO = KpD * D_;    // per-layer u32 offset for Wq/k/v/o planes
    const int WGU = KpD * FF_;   // per-layer offset for gate/up
    const int WDN = KpF * D_;    // per-layer offset for down

    for (int l = 0; l < L_; l++) {
        const float* Wb_l = Wb + (size_t)l * D_ * H_;
        const float* cq_l = conv_q + (size_t)l * D_ * KC;
        const float* ck_l = conv_k + (size_t)l * D_ * KC;
        const float* cv_l = conv_v + (size_t)l * D_ * KC;

        rmsnorm_k<<<T_, 256>>>(h, attn_norm + (size_t)l * D_, x);

        // qkv projections (fused, fp16 split path)
        run_splitA(x, Aah, Aal, TD / 2);
        {
            dim3 grid(D_ / 128, T_ / 64, 3);
            hgemm3_k<<<grid, 128>>>(T_, D_, KpD, Aah, Aal,
                                    Wqh + (size_t)l * WQO, Wql + (size_t)l * WQO,
                                    Wkh + (size_t)l * WQO, Wkl + (size_t)l * WQO,
                                    Wvh + (size_t)l * WQO, Wvl + (size_t)l * WQO,
                                    qp, kp, vp);
        }
        beta_k<<<T_ / 8, 256>>>(x, Wb_l, beta);

        {
            dim3 grid((TD + 255) / 256, 3);
            conv_silu3_k<<<grid, 256>>>(qp, kp, vp, cq_l, ck_l, cv_l, q, k, v);
        }
        {
            dim3 grid(T_ * H_, 2);
            l2norm2_k<<<grid, 64>>>(q, k);
        }

        delta_k<<<H_, 128>>>(q, k, v, beta, o);

        headrms_k<<<T_*H_, 64>>>(o, o_norm_w + (size_t)l * DK_);

        // h += o @ Wo
        run_splitA(o, Aah, Aal, TD / 2);
        run_hgemm(T_, D_, KpD, Aah, Aal,
                  Woh + (size_t)l * WQO, Wol + (size_t)l * WQO, h, 1);

        rmsnorm_k<<<T_, 256>>>(h, mlp_norm + (size_t)l * D_, y);

        // gate/up (fused)
        run_splitA(y, Aah, Aal, TD / 2);
        {
            dim3 grid(FF_ / 128, T_ / 64, 2);
            hgemm3_k<<<grid, 128>>>(T_, FF_, KpD, Aah, Aal,
                                    Wgh + (size_t)l * WGU, Wgl + (size_t)l * WGU,
                                    Wuh + (size_t)l * WGU, Wul + (size_t)l * WGU,
                                    Wuh + (size_t)l * WGU, Wul + (size_t)l * WGU,
                                    gate, up, up);
        }
        silu_mul_k<<<(TF + 255) / 256, 256>>>(gate, up, TF);

        // h += gate @ Wdown
        run_splitA(gate, Aah, Aal, TF / 2);
        run_hgemm(T_, D_, KpF, Aah, Aal,
                  Wdh + (size_t)l * WDN, Wdl + (size_t)l * WDN, h, 1);
    }

    rmsnorm_k<<<T_, 256>>>(h, final_norm, y);

    // lm_head
    run_splitA(y, Aah, Aal, TD / 2);
    run_hgemm(T_, V_, KpD, Aah, Aal, LMh, LMl, logits, 0);

    zero_loss_k<<<1, 1>>>();
    loss_k<<<T_, 256>>>(logits, targets);
    finalize_k<<<1, 1>>>((float*)d_out, (long long)out_size);
}